// round 7
// baseline (speedup 1.0000x reference)
#include <cuda_runtime.h>
#include <math.h>

// Problem dims
#define Nb 64
#define Tt 512
#define Ii 512
#define Hh 1024
#define Oo 512
#define MROWS (Nb*Tt)
#define NH (Nb*Hh)
#define RNN_NCTA 128

typedef unsigned long long ull;

// ---------------- scratch ----------------
__device__ float g_nmaj [(size_t)Tt * NH];      // n-major staging [T][N][H]
__device__ float g_inpT [(size_t)Tt * NH];      // transposed inp [T][H][N]
__device__ float g_hsT  [(size_t)Tt * NH];      // transposed h state [T][H][N]
__device__ float g_tmp  [(size_t)Tt * Nb * Oo];
__device__ float g_out_t[(size_t)Tt * Nb * Oo];
__device__ float g_h0T  [NH];
__device__ unsigned g_l1[16 * 32];              // level-1 counters (128B apart)
__device__ unsigned g_l2;
__device__ volatile unsigned g_bar_gen;

// ---------------- helpers ----------------
__device__ __forceinline__ ull ffma2(ull a, ull b, ull c) {
    ull d;
    asm("fma.rn.f32x2 %0, %1, %2, %3;" : "=l"(d) : "l"(a), "l"(b), "l"(c));
    return d;
}
__device__ __forceinline__ ull addf2(ull a, ull b) {
    ull d;
    asm("add.rn.f32x2 %0, %1, %2;" : "=l"(d) : "l"(a), "l"(b));
    return d;
}
__device__ __forceinline__ float2 unpack2(ull v) {
    float2 r;
    asm("mov.b64 {%0, %1}, %2;" : "=f"(r.x), "=f"(r.y) : "l"(v));
    return r;
}
__device__ __forceinline__ ull dup2(float v) {
    ull r;
    asm("mov.b64 %0, {%1, %1};" : "=l"(r) : "f"(v));
    return r;
}
__device__ __forceinline__ float retanh(float x) {
    return x > 0.f ? tanhf(x) : 0.f;
}
__device__ __forceinline__ unsigned smem_u32(const void* p) {
    return (unsigned)__cvta_generic_to_shared(p);
}
#define CP_ASYNC16(dst, src) \
    asm volatile("cp.async.cg.shared.global [%0], [%1], 16;" :: "r"(dst), "l"(src))
#define CP_COMMIT() asm volatile("cp.async.commit_group;" ::: "memory")
#define CP_WAIT0()  asm volatile("cp.async.wait_group 0;" ::: "memory")

__global__ void reset_barrier_kernel() {
    int t = threadIdx.x;
    if (t < 16 * 32) g_l1[t] = 0u;
    if (t == 0) { g_l2 = 0u; g_bar_gen = 0u; }
}

// two-level tree barrier: 16 groups x 8 CTAs -> 1 x 16. Monotonic counters.
__device__ __forceinline__ void tree_barrier(int bx, unsigned target) {
    __syncthreads();
    if (threadIdx.x == 0) {
        __threadfence();
        unsigned o1 = atomicAdd(&g_l1[(bx >> 3) * 32], 1u);
        if ((o1 & 7u) == 7u) {
            unsigned o2 = atomicAdd(&g_l2, 1u);
            if ((o2 & 15u) == 15u) {
                __threadfence();
                g_bar_gen = target;
            }
        }
        while (g_bar_gen < target) { }
        __threadfence();
    }
    __syncthreads();
}

// h0 [N][H] -> [H][N]
__global__ void transpose64x1024(const float* __restrict__ in, float* __restrict__ out) {
    int i = blockIdx.x * 256 + threadIdx.x;
    int h = i >> 6, n = i & 63;
    out[i] = in[n * Hh + h];
}

// inp [T][N][H] -> [T][H][N].  grid (Tt, 32), block 256; tile 32h x 64n.
__global__ void __launch_bounds__(256) transpose_inp(
    const float* __restrict__ in, float* __restrict__ out)
{
    __shared__ float s[32][65];
    const int t = blockIdx.x;
    const int h0 = blockIdx.y * 32;
    const int tid = threadIdx.x;
    const float* ip = in + (size_t)t * NH;
    float* op = out + (size_t)t * NH;

    int hl = tid & 31;
    int nb = tid >> 5;
#pragma unroll
    for (int i = 0; i < 8; i++) {
        int n = nb * 8 + i;
        s[hl][n] = ip[(size_t)n * Hh + h0 + hl];
    }
    __syncthreads();
    int n4 = (tid & 15) * 4;
    int hr = tid >> 4;
#pragma unroll
    for (int i = 0; i < 2; i++) {
        int h = hr * 2 + i;
        float4 v = make_float4(s[h][n4], s[h][n4 + 1], s[h][n4 + 2], s[h][n4 + 3]);
        *(float4*)(op + (size_t)(h0 + h) * Nb + n4) = v;
    }
}

// ---------------- GEMM: C = act(A * W^T + bias) ----------------
// AMAP : A rows gathered from data [N][T][I] (row r=(t*64+n) -> n*T+t)
// ATMAP: A is [T][K][N] transposed layout
// CMAP : C rows written to [N][T][O]
template<int AMAP, int ATMAP, int CMAP, int RET>
__global__ void __launch_bounds__(256, 2) gemm128(
    const float* __restrict__ A, const float* __restrict__ W,
    const float* __restrict__ bias, float* __restrict__ C,
    int M, int Nc, int K)
{
    __shared__ float As[8][128];
    __shared__ float Bs[8][128];

    const int tid = threadIdx.x;
    const int m0 = blockIdx.x * 128;
    const int n0 = blockIdx.y * 128;

    const int warp = tid >> 5;
    const int lane = tid & 31;
    const int wm = warp & 3;
    const int wn = warp >> 2;
    const int tm = lane & 3;
    const int tn = lane >> 2;

    const int srow = tid >> 1;
    const int sk = (tid & 1) * 4;

    int r = m0 + srow;
    const float* Ap;
    if (AMAP) {
        int nn = r & 63, tt = r >> 6;
        Ap = A + (size_t)(nn * Tt + tt) * K + sk;
    } else if (ATMAP) {
        Ap = A + (size_t)(r >> 6) * K * Nb + (r & 63) + (size_t)sk * Nb;
    } else {
        Ap = A + (size_t)r * K + sk;
    }
    const float* Wp = W + (size_t)(n0 + srow) * K + sk;

    ull acc[4][8];
#pragma unroll
    for (int i = 0; i < 4; i++)
#pragma unroll
        for (int j = 0; j < 8; j++) acc[i][j] = 0ull;

    float4 av;
    if (ATMAP) {
        av.x = Ap[0]; av.y = Ap[Nb]; av.z = Ap[2 * Nb]; av.w = Ap[3 * Nb];
    } else {
        av = *(const float4*)(Ap);
    }
    float4 wv = *(const float4*)(Wp);

    const int aoff = wm * 32 + tm * 8;
    const int boff = wn * 64 + tn * 8;

    for (int k0 = 0; k0 < K; k0 += 8) {
        As[sk + 0][srow] = av.x;
        As[sk + 1][srow] = av.y;
        As[sk + 2][srow] = av.z;
        As[sk + 3][srow] = av.w;
        Bs[sk + 0][srow] = wv.x;
        Bs[sk + 1][srow] = wv.y;
        Bs[sk + 2][srow] = wv.z;
        Bs[sk + 3][srow] = wv.w;
        __syncthreads();
        if (k0 + 8 < K) {
            if (ATMAP) {
                const float* q = Ap + (size_t)(k0 + 8) * Nb;
                av.x = q[0]; av.y = q[Nb]; av.z = q[2 * Nb]; av.w = q[3 * Nb];
            } else {
                av = *(const float4*)(Ap + k0 + 8);
            }
            wv = *(const float4*)(Wp + k0 + 8);
        }
#pragma unroll
        for (int kk = 0; kk < 8; kk++) {
            ulonglong2 a01 = *(const ulonglong2*)&As[kk][aoff];
            ulonglong2 a23 = *(const ulonglong2*)&As[kk][aoff + 4];
            float4 b0 = *(const float4*)&Bs[kk][boff];
            float4 b1 = *(const float4*)&Bs[kk][boff + 4];
            ull avv[4] = { a01.x, a01.y, a23.x, a23.y };
            ull bd[8];
            bd[0] = dup2(b0.x); bd[1] = dup2(b0.y);
            bd[2] = dup2(b0.z); bd[3] = dup2(b0.w);
            bd[4] = dup2(b1.x); bd[5] = dup2(b1.y);
            bd[6] = dup2(b1.z); bd[7] = dup2(b1.w);
#pragma unroll
            for (int i = 0; i < 4; i++)
#pragma unroll
                for (int j = 0; j < 8; j++)
                    acc[i][j] = ffma2(avv[i], bd[j], acc[i][j]);
        }
        __syncthreads();
    }

    float bb[8];
#pragma unroll
    for (int j = 0; j < 8; j++) bb[j] = bias[n0 + boff + j];

#pragma unroll
    for (int i = 0; i < 4; i++) {
        float o0[8], o1[8];
#pragma unroll
        for (int j = 0; j < 8; j++) {
            float2 u = unpack2(acc[i][j]);
            float x0 = u.x + bb[j], x1 = u.y + bb[j];
            if (RET) { x0 = retanh(x0); x1 = retanh(x1); }
            o0[j] = x0; o1[j] = x1;
        }
        int r0 = m0 + aoff + 2 * i;
        int r1 = r0 + 1;
        int cr0 = r0, cr1 = r1;
        if (CMAP) {
            cr0 = (r0 & 63) * Tt + (r0 >> 6);
            cr1 = (r1 & 63) * Tt + (r1 >> 6);
        }
        float4* p0 = (float4*)(C + (size_t)cr0 * Nc + n0 + boff);
        p0[0] = make_float4(o0[0], o0[1], o0[2], o0[3]);
        p0[1] = make_float4(o0[4], o0[5], o0[6], o0[7]);
        float4* p1 = (float4*)(C + (size_t)cr1 * Nc + n0 + boff);
        p1[0] = make_float4(o1[0], o1[1], o1[2], o1[3]);
        p1[1] = make_float4(o1[4], o1[5], o1[6], o1[7]);
    }
}

// ---------------- persistent RNN v4: 512 threads, tree barrier ----------------
// 128 CTAs x 512 thr. CTA gh owns 8 h columns, full K=1024.
// Thread (h_loc=tid&7, kk=(tid>>3)&31, nh=tid>>8): 32 W scalars, 16 f32x2 accs
// over n-pairs [nh*16, nh*16+16). [H][N] global layout, one tree barrier/step.
#define HT_STRIDE 68
#define HT_BUF_FLOATS (128 * HT_STRIDE)          // 8704
#define RED_ROW_ULL 34                           // 272B rows
#define RNN_SMEM_BYTES ((2 * HT_BUF_FLOATS) * 4 + 256 * RED_ROW_ULL * 8)  // 139264

__global__ void __launch_bounds__(512, 1) rnn_persistent(
    const float* __restrict__ h0T, const float* __restrict__ Wh,
    const float* __restrict__ bh, const float* __restrict__ inpT,
    float* __restrict__ hsT)
{
    extern __shared__ float sm[];
    float* buf0 = sm;
    float* buf1 = sm + HT_BUF_FLOATS;
    ull* red = (ull*)(sm + 2 * HT_BUF_FLOATS);

    const int tid = threadIdx.x;
    const int bx = blockIdx.x;
    const int gh = bx;
    const int h_loc = tid & 7;
    const int kk = (tid >> 3) & 31;
    const int nh = tid >> 8;                 // 0/1: which 16 n-pairs
    const int hg = gh * 8 + h_loc;

    // W into registers
    float w[8][4];
#pragma unroll
    for (int c = 0; c < 8; c++)
#pragma unroll
        for (int j = 0; j < 4; j++)
            w[c][j] = Wh[(size_t)hg * Hh + c * 128 + kk + 32 * j];

    // staging offsets (4 pieces/thread)
    int s_sm[4], s_gl[4];
#pragma unroll
    for (int jj = 0; jj < 4; jj++) {
        int idx = jj * 512 + tid;
        int kr = idx >> 4;
        int q4 = (idx & 15) * 4;
        s_sm[jj] = kr * HT_STRIDE + q4;
        s_gl[jj] = kr * Nb + q4;
    }

    // epilogue mapping: warps 0-7 do the reduce (warp = h, lane = n-pair)
    const int wz = tid >> 5;
    const int lane = tid & 31;
    const int hout = gh * 8 + wz;            // valid for wz < 8
    const int n0 = lane * 2;
    const float bia = (wz < 8) ? bh[hout] : 0.f;

    unsigned gen = 0;

    for (int t = 0; t < Tt; ++t) {
        const float* hp = t ? (hsT + (size_t)(t - 1) * NH) : h0T;

        ull acc[16];
#pragma unroll
        for (int p = 0; p < 16; p++) acc[p] = 0ull;

#pragma unroll
        for (int jj = 0; jj < 4; jj++)
            CP_ASYNC16(smem_u32(buf0 + s_sm[jj]), hp + s_gl[jj]);
        CP_COMMIT();
        CP_WAIT0();
        __syncthreads();

#pragma unroll
        for (int c = 0; c < 8; c++) {
            const float* cur = (c & 1) ? buf1 : buf0;
            float* nxt = (c & 1) ? buf0 : buf1;
            if (c < 7) {
                const float* src = hp + (c + 1) * 128 * Nb;
#pragma unroll
                for (int jj = 0; jj < 4; jj++)
                    CP_ASYNC16(smem_u32(nxt + s_sm[jj]), src + s_gl[jj]);
                CP_COMMIT();
            }
#pragma unroll
            for (int j = 0; j < 4; j++) {
                ull wd = dup2(w[c][j]);
                const float* row = cur + (kk + 32 * j) * HT_STRIDE + nh * 32;
#pragma unroll
                for (int q = 0; q < 8; q++) {
                    ulonglong2 v = *(const ulonglong2*)(row + q * 4);
                    acc[2 * q]     = ffma2(v.x, wd, acc[2 * q]);
                    acc[2 * q + 1] = ffma2(v.y, wd, acc[2 * q + 1]);
                }
            }
            if (c < 7) {
                CP_WAIT0();
                __syncthreads();
            }
        }

        // partials -> smem (16B-aligned: row*272B + nh*128B)
        {
            ull* myrow = red + (kk * 8 + h_loc) * RED_ROW_ULL + nh * 16;
#pragma unroll
            for (int i = 0; i < 8; i++) {
                ulonglong2 v2;
                v2.x = acc[2 * i];
                v2.y = acc[2 * i + 1];
                *(ulonglong2*)(myrow + 2 * i) = v2;
            }
        }
        float2 ip;
        if (wz < 8)
            ip = *(const float2*)(inpT + (size_t)t * NH + (size_t)hout * Nb + n0);
        __syncthreads();

        if (wz < 8) {
            // final 32-way k reduce
            ull s = 0ull;
#pragma unroll
            for (int k = 0; k < 32; k++)
                s = addf2(s, red[(k * 8 + wz) * RED_ROW_ULL + lane]);
            float2 u = unpack2(s);
            float r0 = retanh(u.x + ip.x + bia);
            float r1 = retanh(u.y + ip.y + bia);
            *(float2*)(hsT + (size_t)t * NH + (size_t)hout * Nb + n0) = make_float2(r0, r1);
        }

        tree_barrier(bx, ++gen);
    }
}

// ---------------- host ----------------
extern "C" void kernel_launch(void* const* d_in, const int* in_sizes, int n_in,
                              void* d_out, int out_size)
{
    const float* data = (const float*)d_in[0];
    const float* h0v  = (const float*)d_in[1];
    const float* h0m  = (const float*)d_in[2];
    const float* Wi   = (const float*)d_in[3];
    const float* bi   = (const float*)d_in[4];
    const float* Wh   = (const float*)d_in[5];
    const float* bh   = (const float*)d_in[6];
    const float* Wo   = (const float*)d_in[7];
    const float* bo   = (const float*)d_in[8];
    const float* Wt   = (const float*)d_in[9];
    const float* bt   = (const float*)d_in[10];
    const float* Wi2  = (const float*)d_in[11];
    const float* bi2  = (const float*)d_in[12];
    const float* Wh2  = (const float*)d_in[13];
    const float* bh2  = (const float*)d_in[14];
    const float* Wo2  = (const float*)d_in[15];
    const float* bo2  = (const float*)d_in[16];
    float* out = (float*)d_out;

    float *nmaj, *inpT, *hsT, *tmp, *outt, *h0T;
    cudaGetSymbolAddress((void**)&nmaj, g_nmaj);
    cudaGetSymbolAddress((void**)&inpT, g_inpT);
    cudaGetSymbolAddress((void**)&hsT,  g_hsT);
    cudaGetSymbolAddress((void**)&tmp,  g_tmp);
    cudaGetSymbolAddress((void**)&outt, g_out_t);
    cudaGetSymbolAddress((void**)&h0T,  g_h0T);

    cudaFuncSetAttribute(rnn_persistent,
                         cudaFuncAttributeMaxDynamicSharedMemorySize, RNN_SMEM_BYTES);

    dim3 blk(256);
    dim3 rblk(512);
    dim3 tgrid(Tt, Hh / 32);

    // 1) inp_v = data @ Wi^T + bi  (n-major), then transpose to [T][H][N]
    gemm128<1, 0, 0, 0><<<dim3(MROWS / 128, Hh / 128), blk>>>(data, Wi, bi, nmaj, MROWS, Hh, Ii);
    transpose_inp<<<tgrid, blk>>>(nmaj, inpT);
    transpose64x1024<<<256, blk>>>(h0v, h0T);

    // 2) visual RNN (writes hsT)
    reset_barrier_kernel<<<1, 512>>>();
    rnn_persistent<<<RNN_NCTA, rblk, RNN_SMEM_BYTES>>>(h0T, Wh, bh, inpT, hsT);

    // 3) out_v = hs_v @ Wo^T + bo   (A read from transposed hsT)
    gemm128<0, 1, 0, 0><<<dim3(MROWS / 128, Oo / 128), blk>>>(hsT, Wo, bo, tmp, MROWS, Oo, Hh);

    // 4) out_t = retanh(out_v @ Wt^T + bt)
    gemm128<0, 0, 0, 1><<<dim3(MROWS / 128, Oo / 128), blk>>>(tmp, Wt, bt, outt, MROWS, Oo, Oo);

    // 5) inp_m = out_t @ Wi2^T + bi2 (n-major), transpose
    gemm128<0, 0, 0, 0><<<dim3(MROWS / 128, Hh / 128), blk>>>(outt, Wi2, bi2, nmaj, MROWS, Hh, Oo);
    transpose_inp<<<tgrid, blk>>>(nmaj, inpT);
    transpose64x1024<<<256, blk>>>(h0m, h0T);

    // 6) motor RNN (writes hsT)
    reset_barrier_kernel<<<1, 512>>>();
    rnn_persistent<<<RNN_NCTA, rblk, RNN_SMEM_BYTES>>>(h0T, Wh2, bh2, inpT, hsT);

    // 7) out_m[n,t,:] = hs_m @ Wo2^T + bo2
    gemm128<0, 1, 1, 0><<<dim3(MROWS / 128, Oo / 128), blk>>>(hsT, Wo2, bo2, out, MROWS, Oo, Hh);
}

// round 8
// speedup vs baseline: 1.0275x; 1.0275x over previous
#include <cuda_runtime.h>
#include <math.h>

// Problem dims
#define Nb 64
#define Tt 512
#define Ii 512
#define Hh 1024
#define Oo 512
#define MROWS (Nb*Tt)
#define NH (Nb*Hh)
#define RNN_NCTA 128

typedef unsigned long long ull;

// ---------------- scratch ----------------
__device__ float g_nmaj [(size_t)Tt * NH];      // n-major staging [T][N][H]
__device__ float g_inpT [(size_t)Tt * NH];      // transposed inp [T][H][N]
__device__ float g_hsT  [(size_t)Tt * NH];      // transposed h state [T][H][N]
__device__ float g_tmp  [(size_t)Tt * Nb * Oo];
__device__ float g_out_t[(size_t)Tt * Nb * Oo];
__device__ float g_h0T  [NH];
__device__ unsigned g_l1[16 * 32];              // level-1 counters (128B apart)
__device__ unsigned g_l2;
__device__ volatile unsigned g_bar_gen;

// ---------------- helpers ----------------
__device__ __forceinline__ ull ffma2(ull a, ull b, ull c) {
    ull d;
    asm("fma.rn.f32x2 %0, %1, %2, %3;" : "=l"(d) : "l"(a), "l"(b), "l"(c));
    return d;
}
__device__ __forceinline__ ull addf2(ull a, ull b) {
    ull d;
    asm("add.rn.f32x2 %0, %1, %2;" : "=l"(d) : "l"(a), "l"(b));
    return d;
}
__device__ __forceinline__ float2 unpack2(ull v) {
    float2 r;
    asm("mov.b64 {%0, %1}, %2;" : "=f"(r.x), "=f"(r.y) : "l"(v));
    return r;
}
__device__ __forceinline__ ull dup2(float v) {
    ull r;
    asm("mov.b64 %0, {%1, %1};" : "=l"(r) : "f"(v));
    return r;
}
__device__ __forceinline__ float retanh(float x) {
    return x > 0.f ? tanhf(x) : 0.f;
}
__device__ __forceinline__ unsigned smem_u32(const void* p) {
    return (unsigned)__cvta_generic_to_shared(p);
}
#define CP_ASYNC16(dst, src) \
    asm volatile("cp.async.cg.shared.global [%0], [%1], 16;" :: "r"(dst), "l"(src))
#define CP_COMMIT() asm volatile("cp.async.commit_group;" ::: "memory")
#define CP_WAIT0()  asm volatile("cp.async.wait_group 0;" ::: "memory")

__global__ void reset_barrier_kernel() {
    int t = threadIdx.x;
    if (t < 16 * 32) g_l1[t] = 0u;
    if (t == 0) { g_l2 = 0u; g_bar_gen = 0u; }
}

// two-level tree barrier: 16 groups x 8 CTAs -> 1 x 16. Monotonic counters.
__device__ __forceinline__ void tree_barrier(int bx, unsigned target) {
    __syncthreads();
    if (threadIdx.x == 0) {
        __threadfence();
        unsigned o1 = atomicAdd(&g_l1[(bx >> 3) * 32], 1u);
        if ((o1 & 7u) == 7u) {
            unsigned o2 = atomicAdd(&g_l2, 1u);
            if ((o2 & 15u) == 15u) {
                __threadfence();
                g_bar_gen = target;
            }
        }
        while (g_bar_gen < target) { }
        __threadfence();
    }
    __syncthreads();
}

// h0 [N][H] -> [H][N]
__global__ void transpose64x1024(const float* __restrict__ in, float* __restrict__ out) {
    int i = blockIdx.x * 256 + threadIdx.x;
    int h = i >> 6, n = i & 63;
    out[i] = in[n * Hh + h];
}

// inp [T][N][H] -> [T][H][N].  grid (Tt, 32), block 256; tile 32h x 64n.
__global__ void __launch_bounds__(256) transpose_inp(
    const float* __restrict__ in, float* __restrict__ out)
{
    __shared__ float s[32][65];
    const int t = blockIdx.x;
    const int h0 = blockIdx.y * 32;
    const int tid = threadIdx.x;
    const float* ip = in + (size_t)t * NH;
    float* op = out + (size_t)t * NH;

    int hl = tid & 31;
    int nb = tid >> 5;
#pragma unroll
    for (int i = 0; i < 8; i++) {
        int n = nb * 8 + i;
        s[hl][n] = ip[(size_t)n * Hh + h0 + hl];
    }
    __syncthreads();
    int n4 = (tid & 15) * 4;
    int hr = tid >> 4;
#pragma unroll
    for (int i = 0; i < 2; i++) {
        int h = hr * 2 + i;
        float4 v = make_float4(s[h][n4], s[h][n4 + 1], s[h][n4 + 2], s[h][n4 + 3]);
        *(float4*)(op + (size_t)(h0 + h) * Nb + n4) = v;
    }
}

// ---------------- GEMM: C = act(A * W^T + bias) ----------------
template<int AMAP, int ATMAP, int CMAP, int RET>
__global__ void __launch_bounds__(256, 2) gemm128(
    const float* __restrict__ A, const float* __restrict__ W,
    const float* __restrict__ bias, float* __restrict__ C,
    int M, int Nc, int K)
{
    __shared__ float As[8][128];
    __shared__ float Bs[8][128];

    const int tid = threadIdx.x;
    const int m0 = blockIdx.x * 128;
    const int n0 = blockIdx.y * 128;

    const int warp = tid >> 5;
    const int lane = tid & 31;
    const int wm = warp & 3;
    const int wn = warp >> 2;
    const int tm = lane & 3;
    const int tn = lane >> 2;

    const int srow = tid >> 1;
    const int sk = (tid & 1) * 4;

    int r = m0 + srow;
    const float* Ap;
    if (AMAP) {
        int nn = r & 63, tt = r >> 6;
        Ap = A + (size_t)(nn * Tt + tt) * K + sk;
    } else if (ATMAP) {
        Ap = A + (size_t)(r >> 6) * K * Nb + (r & 63) + (size_t)sk * Nb;
    } else {
        Ap = A + (size_t)r * K + sk;
    }
    const float* Wp = W + (size_t)(n0 + srow) * K + sk;

    ull acc[4][8];
#pragma unroll
    for (int i = 0; i < 4; i++)
#pragma unroll
        for (int j = 0; j < 8; j++) acc[i][j] = 0ull;

    float4 av;
    if (ATMAP) {
        av.x = Ap[0]; av.y = Ap[Nb]; av.z = Ap[2 * Nb]; av.w = Ap[3 * Nb];
    } else {
        av = *(const float4*)(Ap);
    }
    float4 wv = *(const float4*)(Wp);

    const int aoff = wm * 32 + tm * 8;
    const int boff = wn * 64 + tn * 8;

    for (int k0 = 0; k0 < K; k0 += 8) {
        As[sk + 0][srow] = av.x;
        As[sk + 1][srow] = av.y;
        As[sk + 2][srow] = av.z;
        As[sk + 3][srow] = av.w;
        Bs[sk + 0][srow] = wv.x;
        Bs[sk + 1][srow] = wv.y;
        Bs[sk + 2][srow] = wv.z;
        Bs[sk + 3][srow] = wv.w;
        __syncthreads();
        if (k0 + 8 < K) {
            if (ATMAP) {
                const float* q = Ap + (size_t)(k0 + 8) * Nb;
                av.x = q[0]; av.y = q[Nb]; av.z = q[2 * Nb]; av.w = q[3 * Nb];
            } else {
                av = *(const float4*)(Ap + k0 + 8);
            }
            wv = *(const float4*)(Wp + k0 + 8);
        }
#pragma unroll
        for (int kk = 0; kk < 8; kk++) {
            ulonglong2 a01 = *(const ulonglong2*)&As[kk][aoff];
            ulonglong2 a23 = *(const ulonglong2*)&As[kk][aoff + 4];
            float4 b0 = *(const float4*)&Bs[kk][boff];
            float4 b1 = *(const float4*)&Bs[kk][boff + 4];
            ull avv[4] = { a01.x, a01.y, a23.x, a23.y };
            ull bd[8];
            bd[0] = dup2(b0.x); bd[1] = dup2(b0.y);
            bd[2] = dup2(b0.z); bd[3] = dup2(b0.w);
            bd[4] = dup2(b1.x); bd[5] = dup2(b1.y);
            bd[6] = dup2(b1.z); bd[7] = dup2(b1.w);
#pragma unroll
            for (int i = 0; i < 4; i++)
#pragma unroll
                for (int j = 0; j < 8; j++)
                    acc[i][j] = ffma2(avv[i], bd[j], acc[i][j]);
        }
        __syncthreads();
    }

    float bb[8];
#pragma unroll
    for (int j = 0; j < 8; j++) bb[j] = bias[n0 + boff + j];

#pragma unroll
    for (int i = 0; i < 4; i++) {
        float o0[8], o1[8];
#pragma unroll
        for (int j = 0; j < 8; j++) {
            float2 u = unpack2(acc[i][j]);
            float x0 = u.x + bb[j], x1 = u.y + bb[j];
            if (RET) { x0 = retanh(x0); x1 = retanh(x1); }
            o0[j] = x0; o1[j] = x1;
        }
        int r0 = m0 + aoff + 2 * i;
        int r1 = r0 + 1;
        int cr0 = r0, cr1 = r1;
        if (CMAP) {
            cr0 = (r0 & 63) * Tt + (r0 >> 6);
            cr1 = (r1 & 63) * Tt + (r1 >> 6);
        }
        float4* p0 = (float4*)(C + (size_t)cr0 * Nc + n0 + boff);
        p0[0] = make_float4(o0[0], o0[1], o0[2], o0[3]);
        p0[1] = make_float4(o0[4], o0[5], o0[6], o0[7]);
        float4* p1 = (float4*)(C + (size_t)cr1 * Nc + n0 + boff);
        p1[0] = make_float4(o1[0], o1[1], o1[2], o1[3]);
        p1[1] = make_float4(o1[4], o1[5], o1[6], o1[7]);
    }
}

// ---------------- persistent RNN v5: 4x h-reuse, LDS-balanced ----------------
// 128 CTAs x 256 thr, CTA gh owns 8 h columns, full K=1024.
// tid = hg(b7) km(b6:5) ng(b4:3) kk(b2:0).
// Thread tile: 4h (hg*4..+3) x 16n (ng*16..+15) x 32k {c*128 + kk + 8*(km*4+j)}.
// W in 128 regs; acc = 32 f32x2 (4h x 8 n-pairs). Each 16B h-load feeds 8 FFMA2.
// Lane map (ng<<3)|kk + 272B-padded rows => all LDS/STS phases conflict-free.
#define HT_STRIDE 68
#define HT_BUF_FLOATS (128 * HT_STRIDE)          // 8704 floats = 34816 B
#define RED_ROW_ULL 258                          // 256 + 2 pad => 2064B rows
#define RNN_SMEM_BYTES (2 * HT_BUF_FLOATS * 4 + 32 * RED_ROW_ULL * 8)  // 135680

__global__ void __launch_bounds__(256, 1) rnn_persistent(
    const float* __restrict__ h0T, const float* __restrict__ Wh,
    const float* __restrict__ bh, const float* __restrict__ inpT,
    float* __restrict__ hsT)
{
    extern __shared__ float sm[];
    float* buf0 = sm;
    float* buf1 = sm + HT_BUF_FLOATS;
    ull* red = (ull*)(sm + 2 * HT_BUF_FLOATS);   // [32 partial-rows][258 ull]

    const int tid = threadIdx.x;
    const int bx = blockIdx.x;
    const int gh = bx;
    const int kk = tid & 7;
    const int ng = (tid >> 3) & 3;
    const int km = (tid >> 5) & 3;
    const int hg = tid >> 7;

    // W into registers: w[hi][c*4+j] = Wh[gh*8+hg*4+hi][c*128 + kk + 8*(km*4+j)]
    float w[4][32];
#pragma unroll
    for (int hi = 0; hi < 4; hi++) {
        const float* wr = Wh + (size_t)(gh * 8 + hg * 4 + hi) * Hh;
#pragma unroll
        for (int c = 0; c < 8; c++)
#pragma unroll
            for (int j = 0; j < 4; j++)
                w[hi][c * 4 + j] = wr[c * 128 + kk + 8 * (km * 4 + j)];
    }

    // staging offsets (8 float4 pieces/thread per 128k-chunk)
    int s_sm[8], s_gl[8];
#pragma unroll
    for (int jj = 0; jj < 8; jj++) {
        int idx = jj * 256 + tid;
        int kr = idx >> 4;
        int q4 = (idx & 15) * 4;
        s_sm[jj] = kr * HT_STRIDE + q4;
        s_gl[jj] = kr * Nb + q4;
    }

    // partial row for reduce
    const int prow = km * 8 + kk;            // 0..31
    // epilogue mapping: warp -> output h, lane -> n-pair
    const int h_o = tid >> 5;                // 0..7
    const int lane = tid & 31;
    const int hout = gh * 8 + h_o;
    const int n0 = lane * 2;
    const float bia = bh[hout];

    unsigned gen = 0;

    for (int t = 0; t < Tt; ++t) {
        const float* hp = t ? (hsT + (size_t)(t - 1) * NH) : h0T;

        ull acc[4][8];
#pragma unroll
        for (int hi = 0; hi < 4; hi++)
#pragma unroll
            for (int p = 0; p < 8; p++) acc[hi][p] = 0ull;

#pragma unroll
        for (int jj = 0; jj < 8; jj++)
            CP_ASYNC16(smem_u32(buf0 + s_sm[jj]), hp + s_gl[jj]);
        CP_COMMIT();
        CP_WAIT0();
        __syncthreads();

#pragma unroll
        for (int c = 0; c < 8; c++) {
            const float* cur = (c & 1) ? buf1 : buf0;
            float* nxt = (c & 1) ? buf0 : buf1;
            if (c < 7) {
                const float* src = hp + (c + 1) * 128 * Nb;
#pragma unroll
                for (int jj = 0; jj < 8; jj++)
                    CP_ASYNC16(smem_u32(nxt + s_sm[jj]), src + s_gl[jj]);
                CP_COMMIT();
            }
#pragma unroll
            for (int j = 0; j < 4; j++) {
                int kl = kk + 8 * (km * 4 + j);
                const float* row = cur + kl * HT_STRIDE + ng * 16;
                ulonglong2 v0 = *(const ulonglong2*)(row);
                ulonglong2 v1 = *(const ulonglong2*)(row + 4);
                ulonglong2 v2 = *(const ulonglong2*)(row + 8);
                ulonglong2 v3 = *(const ulonglong2*)(row + 12);
#pragma unroll
                for (int hi = 0; hi < 4; hi++) {
                    ull wd = dup2(w[hi][c * 4 + j]);
                    acc[hi][0] = ffma2(v0.x, wd, acc[hi][0]);
                    acc[hi][1] = ffma2(v0.y, wd, acc[hi][1]);
                    acc[hi][2] = ffma2(v1.x, wd, acc[hi][2]);
                    acc[hi][3] = ffma2(v1.y, wd, acc[hi][3]);
                    acc[hi][4] = ffma2(v2.x, wd, acc[hi][4]);
                    acc[hi][5] = ffma2(v2.y, wd, acc[hi][5]);
                    acc[hi][6] = ffma2(v3.x, wd, acc[hi][6]);
                    acc[hi][7] = ffma2(v3.y, wd, acc[hi][7]);
                }
            }
            if (c < 7) {
                CP_WAIT0();
                __syncthreads();
            }
        }

        // partials -> smem: red[prow][(hg*4+hi)*32 + ng*8 + npi]
        {
            ull* rb = red + (size_t)prow * RED_ROW_ULL + hg * 128 + ng * 8;
#pragma unroll
            for (int hi = 0; hi < 4; hi++) {
                ulonglong2* p = (ulonglong2*)(rb + hi * 32);
                p[0] = make_ulonglong2(acc[hi][0], acc[hi][1]);
                p[1] = make_ulonglong2(acc[hi][2], acc[hi][3]);
                p[2] = make_ulonglong2(acc[hi][4], acc[hi][5]);
                p[3] = make_ulonglong2(acc[hi][6], acc[hi][7]);
            }
        }
        // coalesced inp prefetch (warp reads 256B)
        float2 ip = *(const float2*)(inpT + (size_t)t * NH + (size_t)hout * Nb + n0);
        __syncthreads();

        // final 32-way k reduce: column (h_o*32 + lane) over 32 rows
        ull s = 0ull;
#pragma unroll
        for (int p = 0; p < 32; p++)
            s = addf2(s, red[(size_t)p * RED_ROW_ULL + h_o * 32 + lane]);
        float2 u = unpack2(s);
        float r0 = retanh(u.x + ip.x + bia);
        float r1 = retanh(u.y + ip.y + bia);

        // coalesced hsT store (warp writes 256B)
        *(float2*)(hsT + (size_t)t * NH + (size_t)hout * Nb + n0) = make_float2(r0, r1);

        tree_barrier(bx, ++gen);
    }
}

// ---------------- host ----------------
extern "C" void kernel_launch(void* const* d_in, const int* in_sizes, int n_in,
                              void* d_out, int out_size)
{
    const float* data = (const float*)d_in[0];
    const float* h0v  = (const float*)d_in[1];
    const float* h0m  = (const float*)d_in[2];
    const float* Wi   = (const float*)d_in[3];
    const float* bi   = (const float*)d_in[4];
    const float* Wh   = (const float*)d_in[5];
    const float* bh   = (const float*)d_in[6];
    const float* Wo   = (const float*)d_in[7];
    const float* bo   = (const float*)d_in[8];
    const float* Wt   = (const float*)d_in[9];
    const float* bt   = (const float*)d_in[10];
    const float* Wi2  = (const float*)d_in[11];
    const float* bi2  = (const float*)d_in[12];
    const float* Wh2  = (const float*)d_in[13];
    const float* bh2  = (const float*)d_in[14];
    const float* Wo2  = (const float*)d_in[15];
    const float* bo2  = (const float*)d_in[16];
    float* out = (float*)d_out;

    float *nmaj, *inpT, *hsT, *tmp, *outt, *h0T;
    cudaGetSymbolAddress((void**)&nmaj, g_nmaj);
    cudaGetSymbolAddress((void**)&inpT, g_inpT);
    cudaGetSymbolAddress((void**)&hsT,  g_hsT);
    cudaGetSymbolAddress((void**)&tmp,  g_tmp);
    cudaGetSymbolAddress((void**)&outt, g_out_t);
    cudaGetSymbolAddress((void**)&h0T,  g_h0T);

    cudaFuncSetAttribute(rnn_persistent,
                         cudaFuncAttributeMaxDynamicSharedMemorySize, RNN_SMEM_BYTES);

    dim3 blk(256);
    dim3 tgrid(Tt, Hh / 32);

    // 1) inp_v = data @ Wi^T + bi  (n-major), then transpose to [T][H][N]
    gemm128<1, 0, 0, 0><<<dim3(MROWS / 128, Hh / 128), blk>>>(data, Wi, bi, nmaj, MROWS, Hh, Ii);
    transpose_inp<<<tgrid, blk>>>(nmaj, inpT);
    transpose64x1024<<<256, blk>>>(h0v, h0T);

    // 2) visual RNN (writes hsT)
    reset_barrier_kernel<<<1, 512>>>();
    rnn_persistent<<<RNN_NCTA, blk, RNN_SMEM_BYTES>>>(h0T, Wh, bh, inpT, hsT);

    // 3) out_v = hs_v @ Wo^T + bo   (A read from transposed hsT)
    gemm128<0, 1, 0, 0><<<dim3(MROWS / 128, Oo / 128), blk>>>(hsT, Wo, bo, tmp, MROWS, Oo, Hh);

    // 4) out_t = retanh(out_v @ Wt^T + bt)
    gemm128<0, 0, 0, 1><<<dim3(MROWS / 128, Oo / 128), blk>>>(tmp, Wt, bt, outt, MROWS, Oo, Oo);

    // 5) inp_m = out_t @ Wi2^T + bi2 (n-major), transpose
    gemm128<0, 0, 0, 0><<<dim3(MROWS / 128, Hh / 128), blk>>>(outt, Wi2, bi2, nmaj, MROWS, Hh, Oo);
    transpose_inp<<<tgrid, blk>>>(nmaj, inpT);
    transpose64x1024<<<256, blk>>>(h0m, h0T);

    // 6) motor RNN (writes hsT)
    reset_barrier_kernel<<<1, 512>>>();
    rnn_persistent<<<RNN_NCTA, blk, RNN_SMEM_BYTES>>>(h0T, Wh2, bh2, inpT, hsT);

    // 7) out_m[n,t,:] = hs_m @ Wo2^T + bo2
    gemm128<0, 1, 1, 0><<<dim3(MROWS / 128, Oo / 128), blk>>>(hsT, Wo2, bo2, out, MROWS, Oo, Hh);
}

// round 10
// speedup vs baseline: 1.4839x; 1.4442x over previous
#include <cuda_runtime.h>
#include <math.h>

// Problem dims
#define Nb 64
#define Tt 512
#define Ii 512
#define Hh 1024
#define Oo 512
#define MROWS (Nb*Tt)
#define NH (Nb*Hh)
#define RNN_NCTA 128

typedef unsigned long long ull;

// ---------------- scratch ----------------
__device__ float g_nmaj [(size_t)Tt * NH];      // n-major staging [T][N][H]
__device__ float g_inpT [(size_t)Tt * NH];      // transposed inp [T][H][64]
__device__ float g_hsT  [(size_t)Tt * NH];      // transposed h state [T][1024][64]
__device__ float g_tmp  [(size_t)Tt * Nb * Oo];
__device__ float g_out_t[(size_t)Tt * Nb * Oo];
__device__ float g_h0T  [NH];
__device__ float g_h0T2 [NH];
__device__ unsigned g_bar_cnt;
__device__ volatile unsigned g_bar_gen;

// ---------------- helpers ----------------
__device__ __forceinline__ ull ffma2(ull a, ull b, ull c) {
    ull d;
    asm("fma.rn.f32x2 %0, %1, %2, %3;" : "=l"(d) : "l"(a), "l"(b), "l"(c));
    return d;
}
__device__ __forceinline__ ull addf2(ull a, ull b) {
    ull d;
    asm("add.rn.f32x2 %0, %1, %2;" : "=l"(d) : "l"(a), "l"(b));
    return d;
}
__device__ __forceinline__ float2 unpack2(ull v) {
    float2 r;
    asm("mov.b64 {%0, %1}, %2;" : "=f"(r.x), "=f"(r.y) : "l"(v));
    return r;
}
__device__ __forceinline__ ull dup2(float v) {
    ull r;
    asm("mov.b64 %0, {%1, %1};" : "=l"(r) : "f"(v));
    return r;
}
__device__ __forceinline__ float retanh(float x) {
    return x > 0.f ? tanhf(x) : 0.f;
}
__device__ __forceinline__ unsigned smem_u32(const void* p) {
    return (unsigned)__cvta_generic_to_shared(p);
}
#define CP_ASYNC16(dst, src) \
    asm volatile("cp.async.cg.shared.global [%0], [%1], 16;" :: "r"(dst), "l"(src))
#define CP_COMMIT() asm volatile("cp.async.commit_group;" ::: "memory")
__device__ __forceinline__ void cp_wait_n(int n) {
    if (n == 0)      asm volatile("cp.async.wait_group 0;" ::: "memory");
    else if (n == 1) asm volatile("cp.async.wait_group 1;" ::: "memory");
    else             asm volatile("cp.async.wait_group 2;" ::: "memory");
}

__global__ void reset_barrier_kernel() {
    g_bar_cnt = 0u;
    g_bar_gen = 0u;
}

__device__ __forceinline__ void grid_barrier(unsigned target) {
    __syncthreads();
    if (threadIdx.x == 0) {
        __threadfence();
        unsigned old = atomicAdd(&g_bar_cnt, 1u);
        if (old == RNN_NCTA - 1) {
            g_bar_cnt = 0u;
            __threadfence();
            g_bar_gen = target;
        } else {
            while (g_bar_gen < target) { }
        }
        __threadfence();
    }
    __syncthreads();
}

// h0 [N][H] -> [H][64]
__global__ void transpose64x1024(const float* __restrict__ in, float* __restrict__ out) {
    int i = blockIdx.x * 256 + threadIdx.x;
    int h = i >> 6, n = i & 63;
    out[i] = in[n * Hh + h];
}

// inp [T][N][H] -> [T][H][64]
__global__ void __launch_bounds__(256) transpose_inp(
    const float* __restrict__ in, float* __restrict__ out)
{
    __shared__ float s[32][65];
    const int t = blockIdx.x;
    const int h0 = blockIdx.y * 32;
    const int tid = threadIdx.x;
    const float* ip = in + (size_t)t * NH;
    float* op = out + (size_t)t * NH;

    int hl = tid & 31;
    int nb = tid >> 5;
#pragma unroll
    for (int i = 0; i < 8; i++) {
        int n = nb * 8 + i;
        s[hl][n] = ip[(size_t)n * Hh + h0 + hl];
    }
    __syncthreads();
    int n4 = (tid & 15) * 4;
    int hr = tid >> 4;
#pragma unroll
    for (int i = 0; i < 2; i++) {
        int h = hr * 2 + i;
        float4 v = make_float4(s[h][n4], s[h][n4 + 1], s[h][n4 + 2], s[h][n4 + 3]);
        *(float4*)(op + (size_t)(h0 + h) * Nb + n4) = v;
    }
}

// ---------------- GEMM: C = act(A * W^T + bias) ----------------
// AMAP : A rows gathered from data [N][T][I]
// ATMAP: A is [T][K][64]: row r=(t*64+n), elem k at t*K*64 + k*64 + n
// CMAP : C rows written to [N][T][O]
template<int AMAP, int ATMAP, int CMAP, int RET>
__global__ void __launch_bounds__(256, 2) gemm128(
    const float* __restrict__ A, const float* __restrict__ W,
    const float* __restrict__ bias, float* __restrict__ C,
    int M, int Nc, int K)
{
    __shared__ float As[8][128];
    __shared__ float Bs[8][128];

    const int tid = threadIdx.x;
    const int m0 = blockIdx.x * 128;
    const int n0 = blockIdx.y * 128;

    const int warp = tid >> 5;
    const int lane = tid & 31;
    const int wm = warp & 3;
    const int wn = warp >> 2;
    const int tm = lane & 3;
    const int tn = lane >> 2;

    const int srow = tid >> 1;
    const int sk = (tid & 1) * 4;

    int r = m0 + srow;
    const float* Ap;
    if (AMAP) {
        int nn = r & 63, tt = r >> 6;
        Ap = A + (size_t)(nn * Tt + tt) * K + sk;
    } else if (ATMAP) {
        Ap = A + (size_t)(r >> 6) * K * Nb + (r & 63) + (size_t)sk * Nb;
    } else {
        Ap = A + (size_t)r * K + sk;
    }
    const float* Wp = W + (size_t)(n0 + srow) * K + sk;

    ull acc[4][8];
#pragma unroll
    for (int i = 0; i < 4; i++)
#pragma unroll
        for (int j = 0; j < 8; j++) acc[i][j] = 0ull;

    float4 av;
    if (ATMAP) {
        av.x = Ap[0]; av.y = Ap[Nb]; av.z = Ap[2 * Nb]; av.w = Ap[3 * Nb];
    } else {
        av = *(const float4*)(Ap);
    }
    float4 wv = *(const float4*)(Wp);

    const int aoff = wm * 32 + tm * 8;
    const int boff = wn * 64 + tn * 8;

    for (int k0 = 0; k0 < K; k0 += 8) {
        As[sk + 0][srow] = av.x;
        As[sk + 1][srow] = av.y;
        As[sk + 2][srow] = av.z;
        As[sk + 3][srow] = av.w;
        Bs[sk + 0][srow] = wv.x;
        Bs[sk + 1][srow] = wv.y;
        Bs[sk + 2][srow] = wv.z;
        Bs[sk + 3][srow] = wv.w;
        __syncthreads();
        if (k0 + 8 < K) {
            if (ATMAP) {
                const float* q = Ap + (size_t)(k0 + 8) * Nb;
                av.x = q[0]; av.y = q[Nb]; av.z = q[2 * Nb]; av.w = q[3 * Nb];
            } else {
                av = *(const float4*)(Ap + k0 + 8);
            }
            wv = *(const float4*)(Wp + k0 + 8);
        }
#pragma unroll
        for (int kk = 0; kk < 8; kk++) {
            ulonglong2 a01 = *(const ulonglong2*)&As[kk][aoff];
            ulonglong2 a23 = *(const ulonglong2*)&As[kk][aoff + 4];
            float4 b0 = *(const float4*)&Bs[kk][boff];
            float4 b1 = *(const float4*)&Bs[kk][boff + 4];
            ull avv[4] = { a01.x, a01.y, a23.x, a23.y };
            ull bd[8];
            bd[0] = dup2(b0.x); bd[1] = dup2(b0.y);
            bd[2] = dup2(b0.z); bd[3] = dup2(b0.w);
            bd[4] = dup2(b1.x); bd[5] = dup2(b1.y);
            bd[6] = dup2(b1.z); bd[7] = dup2(b1.w);
#pragma unroll
            for (int i = 0; i < 4; i++)
#pragma unroll
                for (int j = 0; j < 8; j++)
                    acc[i][j] = ffma2(avv[i], bd[j], acc[i][j]);
        }
        __syncthreads();
    }

    float bb[8];
#pragma unroll
    for (int j = 0; j < 8; j++) bb[j] = bias[n0 + boff + j];

#pragma unroll
    for (int i = 0; i < 4; i++) {
        float o0[8], o1[8];
#pragma unroll
        for (int j = 0; j < 8; j++) {
            float2 u = unpack2(acc[i][j]);
            float x0 = u.x + bb[j], x1 = u.y + bb[j];
            if (RET) { x0 = retanh(x0); x1 = retanh(x1); }
            o0[j] = x0; o1[j] = x1;
        }
        int r0 = m0 + aoff + 2 * i;
        int r1 = r0 + 1;
        int cr0 = r0, cr1 = r1;
        if (CMAP) {
            cr0 = (r0 & 63) * Tt + (r0 >> 6);
            cr1 = (r1 & 63) * Tt + (r1 >> 6);
        }
        float4* p0 = (float4*)(C + (size_t)cr0 * Nc + n0 + boff);
        p0[0] = make_float4(o0[0], o0[1], o0[2], o0[3]);
        p0[1] = make_float4(o0[4], o0[5], o0[6], o0[7]);
        float4* p1 = (float4*)(C + (size_t)cr1 * Nc + n0 + boff);
        p1[0] = make_float4(o1[0], o1[1], o1[2], o1[3]);
        p1[1] = make_float4(o1[4], o1[5], o1[6], o1[7]);
    }
}

// ---------------- persistent RNN v7: hT=8, W-in-smem, depth-3 pipeline ----------
// 128 CTAs x 256 thr. CTA gh owns 8 h cols; W tile (8h x 1024k) in smem once.
// Thread (kw=warp, km2=lane>>3, ng=lane&7): k slice 4 per chunk, all 8 h,
// n = {4ng..4ng+3} U {32+4ng..+3} (4 n-pairs). acc = 8h x 4np f32x2 (64 regs).
// Chunk = contiguous 32KB of hsT[t-1]; 4 buffers, cp.async depth 3.
#define CHUNK_FLOATS 8192
#define WSM_FLOATS 8192
#define RED_ROW_ULL 258
#define RNN_SMEM_BYTES ((4 * CHUNK_FLOATS + WSM_FLOATS) * 4 + 32 * RED_ROW_ULL * 8) // 229888

__global__ void __launch_bounds__(256, 1) rnn_persistent(
    const float* __restrict__ h0T, const float* __restrict__ Wh,
    const float* __restrict__ bh, const float* __restrict__ inpT,
    float* __restrict__ hsT)
{
    extern __shared__ float sm[];
    float* bufs = sm;                              // 4 x 8192 floats
    float* Wsm  = sm + 4 * CHUNK_FLOATS;           // [k][8h]
    ull* red    = (ull*)(sm + 4 * CHUNK_FLOATS + WSM_FLOATS);  // [32][258]

    const int tid = threadIdx.x;
    const int gh = blockIdx.x;
    const int kw = tid >> 5;
    const int lane = tid & 31;
    const int km2 = lane >> 3;          // 0..3
    const int ng = lane & 7;            // 0..7

    // stage W once: Wsm[k*8+h] = Wh[gh*8+h][k]
    for (int idx = tid; idx < 8192; idx += 256) {
        int h = idx >> 10;
        int k = idx & 1023;
        Wsm[k * 8 + h] = Wh[(size_t)(gh * 8 + h) * Hh + k];
    }
    __syncthreads();

    // epilogue mapping
    const int h_o = tid >> 5;
    const int ln = tid & 31;
    const int hout = gh * 8 + h_o;
    const int ej = ln & 3;
    const int eng = ln >> 2;
    const int n0 = (ej >> 1) * 32 + eng * 4 + (ej & 1) * 2;
    const float bia = bh[hout];

    const int prow = kw * 4 + km2;

    unsigned gen = 0;

    for (int t = 0; t < Tt; ++t) {
        const float* hp = t ? (hsT + (size_t)(t - 1) * NH) : h0T;

        ull acc[8][4];
#pragma unroll
        for (int h = 0; h < 8; h++)
#pragma unroll
            for (int p = 0; p < 4; p++) acc[h][p] = 0ull;

        // prologue: stage chunks 0,1,2
#pragma unroll
        for (int c = 0; c < 3; c++) {
            float* dst = bufs + (c & 3) * CHUNK_FLOATS;
            const float* src = hp + c * CHUNK_FLOATS;
#pragma unroll
            for (int j = 0; j < 8; j++) {
                int off = j * 1024 + tid * 4;
                CP_ASYNC16(smem_u32(dst + off), src + off);
            }
            CP_COMMIT();
        }

#pragma unroll
        for (int c = 0; c < 8; c++) {
            cp_wait_n(c < 5 ? 2 : 7 - c);
            __syncthreads();
            if (c + 3 < 8) {
                float* dst = bufs + ((c + 3) & 3) * CHUNK_FLOATS;
                const float* src = hp + (c + 3) * CHUNK_FLOATS;
#pragma unroll
                for (int j = 0; j < 8; j++) {
                    int off = j * 1024 + tid * 4;
                    CP_ASYNC16(smem_u32(dst + off), src + off);
                }
                CP_COMMIT();
            }
            const float* cur = bufs + (c & 3) * CHUNK_FLOATS;
#pragma unroll
            for (int i = 0; i < 4; i++) {
                int krow = kw * 16 + km2 * 4 + i;
                const float* row = cur + krow * 64;
                const float* wp = Wsm + (c * 128 + krow) * 8;
                float4 wa = *(const float4*)(wp);
                float4 wb = *(const float4*)(wp + 4);
                ulonglong2 A = *(const ulonglong2*)(row + ng * 4);
                ulonglong2 B = *(const ulonglong2*)(row + 32 + ng * 4);
                float wf[8] = { wa.x, wa.y, wa.z, wa.w, wb.x, wb.y, wb.z, wb.w };
#pragma unroll
                for (int h = 0; h < 8; h++) {
                    ull wd = dup2(wf[h]);
                    acc[h][0] = ffma2(A.x, wd, acc[h][0]);
                    acc[h][1] = ffma2(A.y, wd, acc[h][1]);
                    acc[h][2] = ffma2(B.x, wd, acc[h][2]);
                    acc[h][3] = ffma2(B.y, wd, acc[h][3]);
                }
            }
        }

        // partials -> smem: red[prow][h*32 + ng*4 + j]
        {
            ull* rb = red + (size_t)prow * RED_ROW_ULL + ng * 4;
#pragma unroll
            for (int h = 0; h < 8; h++) {
                *(ulonglong2*)(rb + h * 32)     = make_ulonglong2(acc[h][0], acc[h][1]);
                *(ulonglong2*)(rb + h * 32 + 2) = make_ulonglong2(acc[h][2], acc[h][3]);
            }
        }
        float2 ip = *(const float2*)(inpT + (size_t)t * NH + (size_t)hout * Nb + n0);
        __syncthreads();

        // final 32-way k reduce over partial rows
        ull s = 0ull;
#pragma unroll
        for (int p = 0; p < 32; p++)
            s = addf2(s, red[(size_t)p * RED_ROW_ULL + h_o * 32 + ln]);
        float2 u = unpack2(s);
        float r0 = retanh(u.x + ip.x + bia);
        float r1 = retanh(u.y + ip.y + bia);

        *(float2*)(hsT + (size_t)t * NH + (size_t)hout * Nb + n0) = make_float2(r0, r1);

        grid_barrier(++gen);
    }
}

// ---------------- host ----------------
extern "C" void kernel_launch(void* const* d_in, const int* in_sizes, int n_in,
                              void* d_out, int out_size)
{
    const float* data = (const float*)d_in[0];
    const float* h0v  = (const float*)d_in[1];
    const float* h0m  = (const float*)d_in[2];
    const float* Wi   = (const float*)d_in[3];
    const float* bi   = (const float*)d_in[4];
    const float* Wh   = (const float*)d_in[5];
    const float* bh   = (const float*)d_in[6];
    const float* Wo   = (const float*)d_in[7];
    const float* bo   = (const float*)d_in[8];
    const float* Wt   = (const float*)d_in[9];
    const float* bt   = (const float*)d_in[10];
    const float* Wi2  = (const float*)d_in[11];
    const float* bi2  = (const float*)d_in[12];
    const float* Wh2  = (const float*)d_in[13];
    const float* bh2  = (const float*)d_in[14];
    const float* Wo2  = (const float*)d_in[15];
    const float* bo2  = (const float*)d_in[16];
    float* out = (float*)d_out;

    float *nmaj, *inpT, *hsT, *tmp, *outt, *h0T, *h0T2;
    cudaGetSymbolAddress((void**)&nmaj, g_nmaj);
    cudaGetSymbolAddress((void**)&inpT, g_inpT);
    cudaGetSymbolAddress((void**)&hsT,  g_hsT);
    cudaGetSymbolAddress((void**)&tmp,  g_tmp);
    cudaGetSymbolAddress((void**)&outt, g_out_t);
    cudaGetSymbolAddress((void**)&h0T,  g_h0T);
    cudaGetSymbolAddress((void**)&h0T2, g_h0T2);

    cudaFuncSetAttribute(rnn_persistent,
                         cudaFuncAttributeMaxDynamicSharedMemorySize, RNN_SMEM_BYTES);

    dim3 blk(256);
    dim3 tgrid(Tt, Hh / 32);

    // launches ordered so ncu (-s 5) profiles rnn_persistent
    transpose64x1024<<<256, blk>>>(h0v, h0T);                                      // 0
    transpose64x1024<<<256, blk>>>(h0m, h0T2);                                     // 1
    gemm128<1, 0, 0, 0><<<dim3(MROWS / 128, Hh / 128), blk>>>(data, Wi, bi, nmaj, MROWS, Hh, Ii); // 2
    transpose_inp<<<tgrid, blk>>>(nmaj, inpT);                                     // 3
    reset_barrier_kernel<<<1, 1>>>();                                              // 4
    rnn_persistent<<<RNN_NCTA, blk, RNN_SMEM_BYTES>>>(h0T, Wh, bh, inpT, hsT);     // 5  <- profiled

    gemm128<0, 1, 0, 0><<<dim3(MROWS / 128, Oo / 128), blk>>>(hsT, Wo, bo, tmp, MROWS, Oo, Hh);
    gemm128<0, 0, 0, 1><<<dim3(MROWS / 128, Oo / 128), blk>>>(tmp, Wt, bt, outt, MROWS, Oo, Oo);
    gemm128<0, 0, 0, 0><<<dim3(MROWS / 128, Hh / 128), blk>>>(outt, Wi2, bi2, nmaj, MROWS, Hh, Oo);
    transpose_inp<<<tgrid, blk>>>(nmaj, inpT);
    reset_barrier_kernel<<<1, 1>>>();
    rnn_persistent<<<RNN_NCTA, blk, RNN_SMEM_BYTES>>>(h0T2, Wh2, bh2, inpT, hsT);
    gemm128<0, 1, 1, 0><<<dim3(MROWS / 128, Oo / 128), blk>>>(hsT, Wo2, bo2, out, MROWS, Oo, Hh);
}